// round 1
// baseline (speedup 1.0000x reference)
#include <cuda_runtime.h>
#include <cstdint>

// MusicRNN: 2-layer LSTM (B=2048, T=256, I=88, H=64) + FC(64->13)
// Plan:
//   K1: precompute layer-0 input projection P0[t][b][h] = float4(i,f,g,o) pre-acts
//       (x @ W_ih0^T + b0), gate-interleaved so K2 loads one LDG.128 per row.
//   K2: persistent fused recurrence. 128 CTAs x 16 batch rows, weights in SMEM
//       (gate-packed float4 [k][h]), h via SMEM double buffer, c in registers,
//       inner products via packed fma.rn.f32x2 (FFMA2), FC fused at the end.

#define BB 2048
#define TT 256
#define II 88
#define HH 64
#define OO 13

// Scratch for the precomputed input projection: [T][B][H] float4 = 512 MB.
__device__ float4 g_P0[(size_t)TT * BB * HH];

// ---------------- packed f32x2 helpers ----------------
__device__ __forceinline__ unsigned long long pack2(float lo, float hi) {
    unsigned long long r;
    asm("mov.b64 %0, {%1, %2};" : "=l"(r) : "f"(lo), "f"(hi));
    return r;
}
__device__ __forceinline__ unsigned long long dup2(float v) {
    unsigned long long r;
    asm("mov.b64 %0, {%1, %1};" : "=l"(r) : "f"(v));
    return r;
}
__device__ __forceinline__ void unpack2(unsigned long long v, float& lo, float& hi) {
    asm("mov.b64 {%0, %1}, %2;" : "=f"(lo), "=f"(hi) : "l"(v));
}
__device__ __forceinline__ void fma2(unsigned long long& d, unsigned long long a,
                                     unsigned long long b) {
    asm("fma.rn.f32x2 %0, %1, %2, %0;" : "+l"(d) : "l"(a), "l"(b));
}

// ---------------- activations (MUFU-based, ~1e-6 abs err) ----------------
__device__ __forceinline__ float sigf(float x) {
    return __fdividef(1.0f, 1.0f + __expf(-x));
}
__device__ __forceinline__ float tanhf_fast(float x) {
    return __fdividef(2.0f, 1.0f + __expf(-2.0f * x)) - 1.0f;
}

__device__ __forceinline__ void lstm_act_pair(
    unsigned long long aI, unsigned long long aF,
    unsigned long long aG, unsigned long long aO,
    float* c, float* hn, int r)
{
    float i0, i1, f0, f1, g0, g1, o0, o1;
    unpack2(aI, i0, i1); unpack2(aF, f0, f1);
    unpack2(aG, g0, g1); unpack2(aO, o0, o1);
    float cc0 = sigf(f0) * c[r]     + sigf(i0) * tanhf_fast(g0);
    float cc1 = sigf(f1) * c[r + 1] + sigf(i1) * tanhf_fast(g1);
    c[r]      = cc0;  hn[r]     = sigf(o0) * tanhf_fast(cc0);
    c[r + 1]  = cc1;  hn[r + 1] = sigf(o1) * tanhf_fast(cc1);
}

// =====================================================================
// K1: input projection.  Grid: B*T/64 CTAs, 512 threads (64 h x 8 rowgroups),
//     8 (b,t)-rows per thread, K=88.
// =====================================================================
#define K1_SMEM ((5696 * 16) + (II * 64 * 4))   // w0p+b0p (float4) + xs (float)

__global__ void __launch_bounds__(512) k1_inproj(
    const float* __restrict__ x, const float* __restrict__ w_ih0,
    const float* __restrict__ b_ih0, const float* __restrict__ b_hh0)
{
    extern __shared__ float4 sm4[];
    float4* w0p = sm4;                      // [88][64] gate-packed
    float4* b0p = sm4 + II * HH;            // [64]
    float*  xs  = (float*)(sm4 + II * HH + HH);  // [88][64]  (k-major, row minor)

    const int tid = threadIdx.x;

    for (int idx = tid; idx < II * HH; idx += 512) {
        int k = idx >> 6, h = idx & 63;
        float4 v;
        v.x = w_ih0[(h      ) * II + k];
        v.y = w_ih0[(h +  64) * II + k];
        v.z = w_ih0[(h + 128) * II + k];
        v.w = w_ih0[(h + 192) * II + k];
        w0p[idx] = v;
    }
    if (tid < HH) {
        float4 v;
        v.x = b_ih0[tid]       + b_hh0[tid];
        v.y = b_ih0[tid +  64] + b_hh0[tid +  64];
        v.z = b_ih0[tid + 128] + b_hh0[tid + 128];
        v.w = b_ih0[tid + 192] + b_hh0[tid + 192];
        b0p[tid] = v;
    }
    const int bt0 = blockIdx.x * 64;   // 64 consecutive (b*T+t) pairs, same b
    for (int idx = tid; idx < 64 * II; idx += 512) {
        int r = idx / II, k = idx - r * II;
        xs[(k << 6) + r] = x[(size_t)bt0 * II + idx];   // fully coalesced read
    }
    __syncthreads();

    const int h  = tid & 63;
    const int r0 = (tid >> 6) * 8;   // 8 rows per thread

    unsigned long long aI[4], aF[4], aG[4], aO[4];
    {
        float4 bv = b0p[h];
        #pragma unroll
        for (int p = 0; p < 4; p++) {
            aI[p] = dup2(bv.x); aF[p] = dup2(bv.y);
            aG[p] = dup2(bv.z); aO[p] = dup2(bv.w);
        }
    }
    #pragma unroll 4
    for (int k = 0; k < II; k++) {
        float4 w = w0p[(k << 6) + h];
        unsigned long long wi = dup2(w.x), wf = dup2(w.y),
                           wg = dup2(w.z), wo = dup2(w.w);
        const unsigned long long* hv =
            (const unsigned long long*)&xs[(k << 6) + r0];  // broadcast loads
        unsigned long long v0 = hv[0], v1 = hv[1], v2 = hv[2], v3 = hv[3];
        fma2(aI[0], wi, v0); fma2(aI[1], wi, v1); fma2(aI[2], wi, v2); fma2(aI[3], wi, v3);
        fma2(aF[0], wf, v0); fma2(aF[1], wf, v1); fma2(aF[2], wf, v2); fma2(aF[3], wf, v3);
        fma2(aG[0], wg, v0); fma2(aG[1], wg, v1); fma2(aG[2], wg, v2); fma2(aG[3], wg, v3);
        fma2(aO[0], wo, v0); fma2(aO[1], wo, v1); fma2(aO[2], wo, v2); fma2(aO[3], wo, v3);
    }
    #pragma unroll
    for (int p = 0; p < 4; p++) {
        float i0, i1, f0, f1, g0, g1, o0, o1;
        unpack2(aI[p], i0, i1); unpack2(aF[p], f0, f1);
        unpack2(aG[p], g0, g1); unpack2(aO[p], o0, o1);
        int bt = bt0 + r0 + 2 * p;
        int t = bt & (TT - 1), b = bt >> 8;
        g_P0[((size_t)t * BB + b) * HH + h] = make_float4(i0, f0, g0, o0);
        bt++; t = bt & (TT - 1); b = bt >> 8;
        g_P0[((size_t)t * BB + b) * HH + h] = make_float4(i1, f1, g1, o1);
    }
}

// =====================================================================
// K2: persistent fused recurrence + FC.
//     Grid: 128 CTAs x 128 threads (64 h x 2 rowgroups), 16 batch rows/CTA.
// =====================================================================
#define K2_SMEM (((3 * 4096 + 64) * 16) + (2048 + 1024) * 4)   // 209920 B

__global__ void __launch_bounds__(128) k2_rnn(
    const float* __restrict__ w_hh0, const float* __restrict__ w_ih1,
    const float* __restrict__ w_hh1, const float* __restrict__ b_ih1,
    const float* __restrict__ b_hh1, const float* __restrict__ fc_w,
    const float* __restrict__ fc_b, float* __restrict__ out)
{
    extern __shared__ float4 sm4[];
    float4* w0p = sm4;                 // [64][64] gate-packed W_hh0
    float4* w1i = sm4 + 4096;          // W_ih1
    float4* w1h = sm4 + 8192;          // W_hh1
    float4* b1p = sm4 + 12288;         // [64] layer-1 bias
    float*  h0buf = (float*)(sm4 + 12352);   // 2 x [64][16] double buffer
    float*  h1s   = h0buf + 2048;            // [64][16]

    const int tid = threadIdx.x;

    for (int idx = tid; idx < 4096; idx += 128) {
        int k = idx >> 6, h = idx & 63;
        float4 v;
        v.x = w_hh0[(h      ) * HH + k]; v.y = w_hh0[(h +  64) * HH + k];
        v.z = w_hh0[(h + 128) * HH + k]; v.w = w_hh0[(h + 192) * HH + k];
        w0p[idx] = v;
        v.x = w_ih1[(h      ) * HH + k]; v.y = w_ih1[(h +  64) * HH + k];
        v.z = w_ih1[(h + 128) * HH + k]; v.w = w_ih1[(h + 192) * HH + k];
        w1i[idx] = v;
        v.x = w_hh1[(h      ) * HH + k]; v.y = w_hh1[(h +  64) * HH + k];
        v.z = w_hh1[(h + 128) * HH + k]; v.w = w_hh1[(h + 192) * HH + k];
        w1h[idx] = v;
    }
    if (tid < HH) {
        float4 v;
        v.x = b_ih1[tid]       + b_hh1[tid];
        v.y = b_ih1[tid +  64] + b_hh1[tid +  64];
        v.z = b_ih1[tid + 128] + b_hh1[tid + 128];
        v.w = b_ih1[tid + 192] + b_hh1[tid + 192];
        b1p[tid] = v;
    }
    for (int idx = tid; idx < 3072; idx += 128) h0buf[idx] = 0.0f;  // h0(both)+h1
    __syncthreads();

    const int h   = tid & 63;
    const int r0  = (tid >> 6) * 8;        // 0 or 8
    const int bR0 = blockIdx.x * 16;       // batch base for this CTA

    float c0[8], c1[8];
    #pragma unroll
    for (int r = 0; r < 8; r++) { c0[r] = 0.0f; c1[r] = 0.0f; }

    // software-pipelined input-projection loads
    float4 xg[8];
    #pragma unroll
    for (int j = 0; j < 8; j++)
        xg[j] = g_P0[(size_t)(bR0 + r0 + j) * HH + h];   // t = 0

    for (int t = 0; t < TT; t++) {
        unsigned long long aI[4], aF[4], aG[4], aO[4];
        #pragma unroll
        for (int p = 0; p < 4; p++) {
            aI[p] = pack2(xg[2 * p].x, xg[2 * p + 1].x);
            aF[p] = pack2(xg[2 * p].y, xg[2 * p + 1].y);
            aG[p] = pack2(xg[2 * p].z, xg[2 * p + 1].z);
            aO[p] = pack2(xg[2 * p].w, xg[2 * p + 1].w);
        }
        {   // prefetch P0 for t+1 (overlaps with layer-0 matvec)
            int tn = (t + 1 < TT) ? (t + 1) : t;
            size_t base = ((size_t)tn * BB + bR0 + r0) * HH + h;
            #pragma unroll
            for (int j = 0; j < 8; j++) xg[j] = g_P0[base + (size_t)j * HH];
        }

        // ---- layer 0: gates += h0(t-1) @ W_hh0^T ----
        const float* hp = h0buf + (t & 1) * 1024;
        #pragma unroll 4
        for (int k = 0; k < HH; k++) {
            float4 w = w0p[(k << 6) + h];
            unsigned long long wi = dup2(w.x), wf = dup2(w.y),
                               wg = dup2(w.z), wo = dup2(w.w);
            const unsigned long long* hv =
                (const unsigned long long*)(hp + (k << 4) + r0);
            unsigned long long v0 = hv[0], v1 = hv[1], v2 = hv[2], v3 = hv[3];
            fma2(aI[0], wi, v0); fma2(aI[1], wi, v1); fma2(aI[2], wi, v2); fma2(aI[3], wi, v3);
            fma2(aF[0], wf, v0); fma2(aF[1], wf, v1); fma2(aF[2], wf, v2); fma2(aF[3], wf, v3);
            fma2(aG[0], wg, v0); fma2(aG[1], wg, v1); fma2(aG[2], wg, v2); fma2(aG[3], wg, v3);
            fma2(aO[0], wo, v0); fma2(aO[1], wo, v1); fma2(aO[2], wo, v2); fma2(aO[3], wo, v3);
        }
        float h0n[8];
        #pragma unroll
        for (int p = 0; p < 4; p++)
            lstm_act_pair(aI[p], aF[p], aG[p], aO[p], c0, h0n, 2 * p);

        float* hw = h0buf + ((t + 1) & 1) * 1024 + (h << 4) + r0;
        ((float4*)hw)[0] = make_float4(h0n[0], h0n[1], h0n[2], h0n[3]);
        ((float4*)hw)[1] = make_float4(h0n[4], h0n[5], h0n[6], h0n[7]);
        __syncthreads();

        // ---- layer 1: gates = b1 + h0(t) @ W_ih1^T + h1(t-1) @ W_hh1^T ----
        {
            float4 bv = b1p[h];
            #pragma unroll
            for (int p = 0; p < 4; p++) {
                aI[p] = dup2(bv.x); aF[p] = dup2(bv.y);
                aG[p] = dup2(bv.z); aO[p] = dup2(bv.w);
            }
        }
        const float* h0c = h0buf + ((t + 1) & 1) * 1024;
        #pragma unroll 4
        for (int k = 0; k < HH; k++) {
            float4 wa = w1i[(k << 6) + h];
            float4 wb = w1h[(k << 6) + h];
            const unsigned long long* av =
                (const unsigned long long*)(h0c + (k << 4) + r0);
            const unsigned long long* uv =
                (const unsigned long long*)(h1s + (k << 4) + r0);
            unsigned long long a0 = av[0], a1 = av[1], a2 = av[2], a3 = av[3];
            unsigned long long u0 = uv[0], u1 = uv[1], u2 = uv[2], u3 = uv[3];
            unsigned long long wi = dup2(wa.x), wf = dup2(wa.y),
                               wg = dup2(wa.z), wo = dup2(wa.w);
            fma2(aI[0], wi, a0); fma2(aI[1], wi, a1); fma2(aI[2], wi, a2); fma2(aI[3], wi, a3);
            fma2(aF[0], wf, a0); fma2(aF[1], wf, a1); fma2(aF[2], wf, a2); fma2(aF[3], wf, a3);
            fma2(aG[0], wg, a0); fma2(aG[1], wg, a1); fma2(aG[2], wg, a2); fma2(aG[3], wg, a3);
            fma2(aO[0], wo, a0); fma2(aO[1], wo, a1); fma2(aO[2], wo, a2); fma2(aO[3], wo, a3);
            wi = dup2(wb.x); wf = dup2(wb.y); wg = dup2(wb.z); wo = dup2(wb.w);
            fma2(aI[0], wi, u0); fma2(aI[1], wi, u1); fma2(aI[2], wi, u2); fma2(aI[3], wi, u3);
            fma2(aF[0], wf, u0); fma2(aF[1], wf, u1); fma2(aF[2], wf, u2); fma2(aF[3], wf, u3);
            fma2(aG[0], wg, u0); fma2(aG[1], wg, u1); fma2(aG[2], wg, u2); fma2(aG[3], wg, u3);
            fma2(aO[0], wo, u0); fma2(aO[1], wo, u1); fma2(aO[2], wo, u2); fma2(aO[3], wo, u3);
        }
        float h1n[8];
        #pragma unroll
        for (int p = 0; p < 4; p++)
            lstm_act_pair(aI[p], aF[p], aG[p], aO[p], c1, h1n, 2 * p);

        __syncthreads();   // all reads of h1s(t-1) done before overwrite
        float* hw1 = h1s + (h << 4) + r0;
        ((float4*)hw1)[0] = make_float4(h1n[0], h1n[1], h1n[2], h1n[3]);
        ((float4*)hw1)[1] = make_float4(h1n[4], h1n[5], h1n[6], h1n[7]);
    }
    __syncthreads();

    // ---- FC head: out[b][o] = h1 . fc_w[o] + fc_b[o] ----
    for (int idx = tid; idx < 16 * OO; idx += 128) {
        int o = idx >> 4, r = idx & 15;
        float s = fc_b[o];
        #pragma unroll 8
        for (int k = 0; k < HH; k++)
            s += fc_w[o * HH + k] * h1s[(k << 4) + r];
        out[(size_t)(bR0 + r) * OO + o] = s;
    }
}

// =====================================================================
extern "C" void kernel_launch(void* const* d_in, const int* in_sizes, int n_in,
                              void* d_out, int out_size)
{
    (void)in_sizes; (void)n_in; (void)out_size;
    const float* x     = (const float*)d_in[0];
    const float* w_ih0 = (const float*)d_in[1];
    const float* w_hh0 = (const float*)d_in[2];
    const float* b_ih0 = (const float*)d_in[3];
    const float* b_hh0 = (const float*)d_in[4];
    const float* w_ih1 = (const float*)d_in[5];
    const float* w_hh1 = (const float*)d_in[6];
    const float* b_ih1 = (const float*)d_in[7];
    const float* b_hh1 = (const float*)d_in[8];
    const float* fc_w  = (const float*)d_in[9];
    const float* fc_b  = (const float*)d_in[10];
    float* out = (float*)d_out;

    cudaFuncSetAttribute(k1_inproj, cudaFuncAttributeMaxDynamicSharedMemorySize, K1_SMEM);
    cudaFuncSetAttribute(k2_rnn,    cudaFuncAttributeMaxDynamicSharedMemorySize, K2_SMEM);

    k1_inproj<<<(BB * TT) / 64, 512, K1_SMEM>>>(x, w_ih0, b_ih0, b_hh0);
    k2_rnn<<<BB / 16, 128, K2_SMEM>>>(w_hh0, w_ih1, w_hh1, b_ih1, b_hh1,
                                      fc_w, fc_b, out);
}